// round 13
// baseline (speedup 1.0000x reference)
#include <cuda_runtime.h>
#include <cuda_bf16.h>
#include <cstdint>

#define DD 128
#define NODES_MAX 100000
#define EDGES_MAX 1600000
#define SCAN_N (NODES_MAX + 1)
#define SCAN_CHUNK 1024

// ---------------- device scratch (no runtime allocation) -------------------
__device__ float  g_h[(size_t)NODES_MAX * DD];
__device__ int2   g_edge[EDGES_MAX];
__device__ int    g_esrc[EDGES_MAX];
__device__ int    g_rowptr[SCAN_N];
__device__ int    g_pos[NODES_MAX];
__device__ int    g_bsum[128];
__device__ int    g_is64;
// bf16 hi/lo weights, row-major [o][k] (the exact B layout row.col mma wants)
__device__ __align__(16) __nv_bfloat16 g_Whi[2][DD * DD];
__device__ __align__(16) __nv_bfloat16 g_Wlo[2][DD * DD];

// ---------------- warp-mma helpers (sm_80+ PTX, valid on compute_100) ------
__device__ __forceinline__ uint32_t smem_u32(const void* p) {
    uint32_t a;
    asm("{ .reg .u64 t; cvta.to.shared.u64 t, %1; cvt.u32.u64 %0, t; }"
        : "=r"(a) : "l"(p));
    return a;
}
__device__ __forceinline__ void ldm_x4(uint32_t& r0, uint32_t& r1,
                                       uint32_t& r2, uint32_t& r3,
                                       uint32_t addr) {
    asm volatile("ldmatrix.sync.aligned.m8n8.x4.shared.b16 {%0,%1,%2,%3}, [%4];"
                 : "=r"(r0), "=r"(r1), "=r"(r2), "=r"(r3) : "r"(addr));
}
__device__ __forceinline__ void mma_bf16(float* c, const uint32_t* a,
                                         uint32_t b0, uint32_t b1) {
    asm volatile(
        "mma.sync.aligned.m16n8k16.row.col.f32.bf16.bf16.f32 "
        "{%0,%1,%2,%3}, {%4,%5,%6,%7}, {%8,%9}, {%0,%1,%2,%3};"
        : "+f"(c[0]), "+f"(c[1]), "+f"(c[2]), "+f"(c[3])
        : "r"(a[0]), "r"(a[1]), "r"(a[2]), "r"(a[3]), "r"(b0), "r"(b1));
}

// ---------------- CSR build pipeline (unchanged) ---------------------------
__global__ void detect_kernel(const void* ei, int n_check, int n_nodes) {
    const long long* p = (const long long*)ei;
    int ok = 1;
    for (int i = 0; i < n_check; i++) {
        long long v = p[i];
        if (v < 0 || v >= n_nodes) { ok = 0; break; }
    }
    g_is64 = ok;
}

__global__ void zero_cnt_kernel(int n) {
    int i = blockIdx.x * blockDim.x + threadIdx.x;
    if (i < n) g_rowptr[i] = 0;
}

__global__ void convert_hist_kernel(const void* ei, int E, int N) {
    int e = blockIdx.x * blockDim.x + threadIdx.x;
    if (e >= E) return;
    int s, d;
    if (g_is64) {
        const long long* p = (const long long*)ei;
        s = (int)p[e];
        d = (int)p[(size_t)E + e];
    } else {
        const int* p = (const int*)ei;
        s = p[e];
        d = p[E + e];
    }
    if ((unsigned)s >= (unsigned)N) s = 0;
    if ((unsigned)d >= (unsigned)N) d = 0;
    g_edge[e] = make_int2(s, d);
    atomicAdd(&g_rowptr[d + 1], 1);
}

__global__ void scan1_kernel(int n) {
    __shared__ int sh[SCAN_CHUNK];
    int i = blockIdx.x * SCAN_CHUNK + threadIdx.x;
    sh[threadIdx.x] = (i < n) ? g_rowptr[i] : 0;
    __syncthreads();
    for (int off = 1; off < SCAN_CHUNK; off <<= 1) {
        int t = (threadIdx.x >= off) ? sh[threadIdx.x - off] : 0;
        __syncthreads();
        sh[threadIdx.x] += t;
        __syncthreads();
    }
    if (i < n) g_rowptr[i] = sh[threadIdx.x];
    if (threadIdx.x == SCAN_CHUNK - 1) g_bsum[blockIdx.x] = sh[threadIdx.x];
}

__global__ void scan2_kernel(int nb) {
    int lane = threadIdx.x;
    int carry = 0;
    for (int base = 0; base < nb; base += 32) {
        int i = base + lane;
        int orig = (i < nb) ? g_bsum[i] : 0;
        int v = orig;
#pragma unroll
        for (int off = 1; off < 32; off <<= 1) {
            int t = __shfl_up_sync(0xffffffffu, v, off);
            if (lane >= off) v += t;
        }
        if (i < nb) g_bsum[i] = carry + v - orig;
        carry += __shfl_sync(0xffffffffu, v, 31);
    }
}

__global__ void scan3_kernel(int n, int N) {
    int i = blockIdx.x * blockDim.x + threadIdx.x;
    if (i >= n) return;
    int v = g_rowptr[i] + g_bsum[i >> 10];
    g_rowptr[i] = v;
    if (i < N) g_pos[i] = v;
}

__global__ void place_kernel(int E) {
    int e = blockIdx.x * blockDim.x + threadIdx.x;
    if (e >= E) return;
    int2 ed = g_edge[e];
    int p = atomicAdd(&g_pos[ed.y], 1);
    g_esrc[p] = ed.x;
}

// Split weights into bf16 hi/lo (row-major [o][k]).
__global__ void bpack_kernel(const float* __restrict__ W1,
                             const float* __restrict__ W2) {
    for (int i = blockIdx.x * blockDim.x + threadIdx.x; i < 2 * DD * DD;
         i += gridDim.x * blockDim.x) {
        int which = i >> 14;
        int j = i & 16383;
        float w = (which ? W2 : W1)[j];
        __nv_bfloat16 hi = __float2bfloat16(w);
        __nv_bfloat16 lo = __float2bfloat16(w - __bfloat162float(hi));
        g_Whi[which][j] = hi;
        g_Wlo[which][j] = lo;
    }
}

// ---------------- fused layer: CSR-aggregate + bf16 mma GEMM + bias + ReLU -
// CTA: 64 nodes. Phase 1: 8 warps x 8 nodes, warp-per-node gather-sum into
// registers (lane owns float4, 4-deep MLP), split to bf16 hi/lo into the mma
// A tile. Phase 2: verified 64x128 mma.sync tile (8 warps, 2m x 4n blocks,
// warp tile 32x32). acc += Ahi*Whi + Alo*Whi + Ahi*Wlo.
// 104KB smem -> 2 CTAs/SM; CTAs in gather phase overlap CTAs in mma phase.
#define PITCH 136
#define TILE_M 64
#define SM_AHI 0
#define SM_ALO (TILE_M * PITCH)
#define SM_WHI (2 * TILE_M * PITCH)
#define SM_WLO (2 * TILE_M * PITCH + 128 * PITCH)
#define GSM_TOTAL ((2 * TILE_M + 2 * 128) * PITCH * (int)sizeof(__nv_bfloat16))

__global__ __launch_bounds__(256, 2)
void fused_layer(const float* __restrict__ X,
                 const __nv_bfloat16* __restrict__ Whi,
                 const __nv_bfloat16* __restrict__ Wlo,
                 const float* __restrict__ bias, float* __restrict__ out,
                 int N) {
    extern __shared__ __nv_bfloat16 smem[];
    const uint32_t sb = smem_u32(smem);
    const int tid = threadIdx.x;
    const int lane = tid & 31;
    const int wid = tid >> 5;
    const int row0 = blockIdx.x * TILE_M;

    // W tiles first (issue global loads early; overlap with gather)
    for (int i = tid; i < 128 * 16; i += 256) {
        int r = i >> 4;
        int q = (i & 15) * 8;
        *(uint4*)(smem + SM_WHI + r * PITCH + q) = *(const uint4*)(Whi + r * DD + q);
        *(uint4*)(smem + SM_WLO + r * PITCH + q) = *(const uint4*)(Wlo + r * DD + q);
    }

    // Phase 1: aggregate 8 nodes per warp; lane owns floats [lane*4, lane*4+4)
    const int nbase = wid * 8;
#pragma unroll
    for (int t = 0; t < 8; t++) {
        int node = row0 + nbase + t;
        float4 a0 = make_float4(0.f, 0.f, 0.f, 0.f), a1 = a0, a2 = a0, a3 = a0;
        if (node < N) {
            int j   = __ldg(&g_rowptr[node]);
            int end = __ldg(&g_rowptr[node + 1]);
            for (; j + 3 < end; j += 4) {
                int s0 = g_esrc[j], s1 = g_esrc[j + 1];
                int s2 = g_esrc[j + 2], s3 = g_esrc[j + 3];
                float4 v0 = *(const float4*)(X + (size_t)s0 * DD + lane * 4);
                float4 v1 = *(const float4*)(X + (size_t)s1 * DD + lane * 4);
                float4 v2 = *(const float4*)(X + (size_t)s2 * DD + lane * 4);
                float4 v3 = *(const float4*)(X + (size_t)s3 * DD + lane * 4);
                a0.x += v0.x; a0.y += v0.y; a0.z += v0.z; a0.w += v0.w;
                a1.x += v1.x; a1.y += v1.y; a1.z += v1.z; a1.w += v1.w;
                a2.x += v2.x; a2.y += v2.y; a2.z += v2.z; a2.w += v2.w;
                a3.x += v3.x; a3.y += v3.y; a3.z += v3.z; a3.w += v3.w;
            }
            for (; j < end; j++) {
                int s = g_esrc[j];
                float4 v = *(const float4*)(X + (size_t)s * DD + lane * 4);
                a0.x += v.x; a0.y += v.y; a0.z += v.z; a0.w += v.w;
            }
            a0.x += a1.x + a2.x + a3.x;
            a0.y += a1.y + a2.y + a3.y;
            a0.z += a1.z + a2.z + a3.z;
            a0.w += a1.w + a2.w + a3.w;
        }
        // split fp32 -> bf16 hi/lo, store into mma A tile
        __nv_bfloat16 hx = __float2bfloat16(a0.x), hy = __float2bfloat16(a0.y);
        __nv_bfloat16 hz = __float2bfloat16(a0.z), hw = __float2bfloat16(a0.w);
        __nv_bfloat16 lx = __float2bfloat16(a0.x - __bfloat162float(hx));
        __nv_bfloat16 ly = __float2bfloat16(a0.y - __bfloat162float(hy));
        __nv_bfloat16 lz = __float2bfloat16(a0.z - __bfloat162float(hz));
        __nv_bfloat16 lw = __float2bfloat16(a0.w - __bfloat162float(hw));
        int off = (nbase + t) * PITCH + lane * 4;
        *(ushort2*)(smem + SM_AHI + off) =
            make_ushort2(__bfloat16_as_ushort(hx), __bfloat16_as_ushort(hy));
        *(ushort2*)(smem + SM_AHI + off + 2) =
            make_ushort2(__bfloat16_as_ushort(hz), __bfloat16_as_ushort(hw));
        *(ushort2*)(smem + SM_ALO + off) =
            make_ushort2(__bfloat16_as_ushort(lx), __bfloat16_as_ushort(ly));
        *(ushort2*)(smem + SM_ALO + off + 2) =
            make_ushort2(__bfloat16_as_ushort(lz), __bfloat16_as_ushort(lw));
    }
    __syncthreads();

    // Phase 2: mma (identical to R10's verified 64x128 tile)
    const int wm0 = (wid & 1) * 32;
    const int wc0 = (wid >> 1) * 32;

    float acc[2][4][4];
#pragma unroll
    for (int m = 0; m < 2; m++)
#pragma unroll
        for (int n = 0; n < 4; n++)
#pragma unroll
            for (int q = 0; q < 4; q++) acc[m][n][q] = 0.f;

    const int lrow = lane & 15;
    const int lkof = (lane >> 4) * 8;

#pragma unroll
    for (int kk = 0; kk < 8; kk++) {
        const int k0 = kk * 16 + lkof;
        uint32_t ah[2][4], al[2][4], bh[2][4], bl[2][4];
#pragma unroll
        for (int mt = 0; mt < 2; mt++) {
            uint32_t ra = sb + (uint32_t)(((wm0 + mt * 16 + lrow) * PITCH + k0) * 2);
            ldm_x4(ah[mt][0], ah[mt][1], ah[mt][2], ah[mt][3], ra + SM_AHI * 2);
            ldm_x4(al[mt][0], al[mt][1], al[mt][2], al[mt][3], ra + SM_ALO * 2);
        }
#pragma unroll
        for (int np = 0; np < 2; np++) {
            uint32_t rb = sb + (uint32_t)(((wc0 + np * 16 + lrow) * PITCH + k0) * 2);
            ldm_x4(bh[np][0], bh[np][1], bh[np][2], bh[np][3], rb + SM_WHI * 2);
            ldm_x4(bl[np][0], bl[np][1], bl[np][2], bl[np][3], rb + SM_WLO * 2);
        }
#pragma unroll
        for (int mt = 0; mt < 2; mt++)
#pragma unroll
            for (int np = 0; np < 2; np++) {
                mma_bf16(acc[mt][2 * np],     ah[mt], bh[np][0], bh[np][2]);
                mma_bf16(acc[mt][2 * np + 1], ah[mt], bh[np][1], bh[np][3]);
                mma_bf16(acc[mt][2 * np],     al[mt], bh[np][0], bh[np][2]);
                mma_bf16(acc[mt][2 * np + 1], al[mt], bh[np][1], bh[np][3]);
                mma_bf16(acc[mt][2 * np],     ah[mt], bl[np][0], bl[np][2]);
                mma_bf16(acc[mt][2 * np + 1], ah[mt], bl[np][1], bl[np][3]);
            }
    }

    // Epilogue: bias + ReLU
    const int erow = lane >> 2;
    const int ecol = (lane & 3) * 2;
    float bb[4][2];
#pragma unroll
    for (int nt = 0; nt < 4; nt++) {
        bb[nt][0] = bias[wc0 + nt * 8 + ecol];
        bb[nt][1] = bias[wc0 + nt * 8 + ecol + 1];
    }
#pragma unroll
    for (int mt = 0; mt < 2; mt++) {
#pragma unroll
        for (int half = 0; half < 2; half++) {
            int gr = row0 + wm0 + mt * 16 + erow + half * 8;
            if (gr < N) {
                float* op = out + (size_t)gr * DD + wc0;
#pragma unroll
                for (int nt = 0; nt < 4; nt++) {
                    float2 o;
                    o.x = fmaxf(acc[mt][nt][2 * half]     + bb[nt][0], 0.f);
                    o.y = fmaxf(acc[mt][nt][2 * half + 1] + bb[nt][1], 0.f);
                    *(float2*)(op + nt * 8 + ecol) = o;
                }
            }
        }
    }
}

// ---------------------------------------------------------------------------
extern "C" void kernel_launch(void* const* d_in, const int* in_sizes, int n_in,
                              void* d_out, int out_size) {
    const float* x  = (const float*)d_in[0];
    const void*  ei = d_in[1];
    const float* W1 = (const float*)d_in[2];
    const float* b1 = (const float*)d_in[3];
    const float* W2 = (const float*)d_in[4];
    const float* b2 = (const float*)d_in[5];
    float* out      = (float*)d_out;

    int N = in_sizes[0] / DD;
    int E = in_sizes[1] / 2;

    float* h;
    __nv_bfloat16 *wh1, *wl1, *wh2, *wl2;
    cudaGetSymbolAddress((void**)&h, g_h);
    cudaGetSymbolAddress((void**)&wh1, g_Whi);
    cudaGetSymbolAddress((void**)&wl1, g_Wlo);
    wh2 = wh1 + DD * DD;
    wl2 = wl1 + DD * DD;

    cudaFuncSetAttribute(fused_layer, cudaFuncAttributeMaxDynamicSharedMemorySize,
                         GSM_TOTAL);

    int n       = N + 1;
    int nb      = (n + SCAN_CHUNK - 1) / SCAN_CHUNK;
    int cgrid   = (E + 255) / 256;
    int ggrid   = (N + TILE_M - 1) / TILE_M;
    int n_check = E < 8 ? E : 8;

    // Build CSR + packed weights (once; reused by both layers)
    detect_kernel<<<1, 1>>>(ei, n_check, N);
    zero_cnt_kernel<<<(n + 255) / 256, 256>>>(n);
    convert_hist_kernel<<<cgrid, 256>>>(ei, E, N);
    scan1_kernel<<<nb, SCAN_CHUNK>>>(n);
    scan2_kernel<<<1, 32>>>(nb);
    scan3_kernel<<<(n + 255) / 256, 256>>>(n, N);
    place_kernel<<<cgrid, 256>>>(E);
    bpack_kernel<<<64, 256>>>(W1, W2);

    // Layer 1 (fused aggregate + GEMM + bias + ReLU)
    fused_layer<<<ggrid, 256, GSM_TOTAL>>>(x, wh1, wl1, b1, h, N);
    // Layer 2
    fused_layer<<<ggrid, 256, GSM_TOTAL>>>(h, wh2, wl2, b2, out, N);
}

// round 16
// speedup vs baseline: 1.1781x; 1.1781x over previous
#include <cuda_runtime.h>
#include <cuda_bf16.h>
#include <cstdint>

#define DD 128
#define NODES_MAX 100000
#define EDGES_MAX 1600000
#define SCAN_N (NODES_MAX + 1)
#define SCAN_CHUNK 1024

// ---------------- device scratch (no runtime allocation) -------------------
__device__ float  g_h[(size_t)NODES_MAX * DD];
__device__ __align__(16) __nv_bfloat16 g_aggh[(size_t)NODES_MAX * DD];
__device__ __align__(16) __nv_bfloat16 g_agglo[(size_t)NODES_MAX * DD];
__device__ int2   g_edge[EDGES_MAX];
__device__ int    g_esrc[EDGES_MAX];
__device__ int    g_rowptr[SCAN_N];
__device__ int    g_pos[NODES_MAX];
__device__ int    g_bsum[128];
__device__ int    g_is64;
__device__ __align__(16) __nv_bfloat16 g_Whi[2][DD * DD];
__device__ __align__(16) __nv_bfloat16 g_Wlo[2][DD * DD];

// ---------------- warp-mma helpers (sm_80+ PTX, valid on compute_100) ------
__device__ __forceinline__ uint32_t smem_u32(const void* p) {
    uint32_t a;
    asm("{ .reg .u64 t; cvta.to.shared.u64 t, %1; cvt.u32.u64 %0, t; }"
        : "=r"(a) : "l"(p));
    return a;
}
__device__ __forceinline__ void ldm_x4(uint32_t& r0, uint32_t& r1,
                                       uint32_t& r2, uint32_t& r3,
                                       uint32_t addr) {
    asm volatile("ldmatrix.sync.aligned.m8n8.x4.shared.b16 {%0,%1,%2,%3}, [%4];"
                 : "=r"(r0), "=r"(r1), "=r"(r2), "=r"(r3) : "r"(addr));
}
__device__ __forceinline__ void mma_bf16(float* c, const uint32_t* a,
                                         uint32_t b0, uint32_t b1) {
    asm volatile(
        "mma.sync.aligned.m16n8k16.row.col.f32.bf16.bf16.f32 "
        "{%0,%1,%2,%3}, {%4,%5,%6,%7}, {%8,%9}, {%0,%1,%2,%3};"
        : "+f"(c[0]), "+f"(c[1]), "+f"(c[2]), "+f"(c[3])
        : "r"(a[0]), "r"(a[1]), "r"(a[2]), "r"(a[3]), "r"(b0), "r"(b1));
}

// ---------------- CSR build pipeline (unchanged, validated) ----------------
__global__ void detect_kernel(const void* ei, int n_check, int n_nodes) {
    const long long* p = (const long long*)ei;
    int ok = 1;
    for (int i = 0; i < n_check; i++) {
        long long v = p[i];
        if (v < 0 || v >= n_nodes) { ok = 0; break; }
    }
    g_is64 = ok;
}

__global__ void zero_cnt_kernel(int n) {
    int i = blockIdx.x * blockDim.x + threadIdx.x;
    if (i < n) g_rowptr[i] = 0;
}

__global__ void convert_hist_kernel(const void* ei, int E, int N) {
    int e = blockIdx.x * blockDim.x + threadIdx.x;
    if (e >= E) return;
    int s, d;
    if (g_is64) {
        const long long* p = (const long long*)ei;
        s = (int)p[e];
        d = (int)p[(size_t)E + e];
    } else {
        const int* p = (const int*)ei;
        s = p[e];
        d = p[E + e];
    }
    if ((unsigned)s >= (unsigned)N) s = 0;
    if ((unsigned)d >= (unsigned)N) d = 0;
    g_edge[e] = make_int2(s, d);
    atomicAdd(&g_rowptr[d + 1], 1);
}

__global__ void scan1_kernel(int n) {
    __shared__ int sh[SCAN_CHUNK];
    int i = blockIdx.x * SCAN_CHUNK + threadIdx.x;
    sh[threadIdx.x] = (i < n) ? g_rowptr[i] : 0;
    __syncthreads();
    for (int off = 1; off < SCAN_CHUNK; off <<= 1) {
        int t = (threadIdx.x >= off) ? sh[threadIdx.x - off] : 0;
        __syncthreads();
        sh[threadIdx.x] += t;
        __syncthreads();
    }
    if (i < n) g_rowptr[i] = sh[threadIdx.x];
    if (threadIdx.x == SCAN_CHUNK - 1) g_bsum[blockIdx.x] = sh[threadIdx.x];
}

__global__ void scan2_kernel(int nb) {
    int lane = threadIdx.x;
    int carry = 0;
    for (int base = 0; base < nb; base += 32) {
        int i = base + lane;
        int orig = (i < nb) ? g_bsum[i] : 0;
        int v = orig;
#pragma unroll
        for (int off = 1; off < 32; off <<= 1) {
            int t = __shfl_up_sync(0xffffffffu, v, off);
            if (lane >= off) v += t;
        }
        if (i < nb) g_bsum[i] = carry + v - orig;
        carry += __shfl_sync(0xffffffffu, v, 31);
    }
}

__global__ void scan3_kernel(int n, int N) {
    int i = blockIdx.x * blockDim.x + threadIdx.x;
    if (i >= n) return;
    int v = g_rowptr[i] + g_bsum[i >> 10];
    g_rowptr[i] = v;
    if (i < N) g_pos[i] = v;
}

__global__ void place_kernel(int E) {
    int e = blockIdx.x * blockDim.x + threadIdx.x;
    if (e >= E) return;
    int2 ed = g_edge[e];
    int p = atomicAdd(&g_pos[ed.y], 1);
    g_esrc[p] = ed.x;
}

// Split weights into bf16 hi/lo (row-major [o][k]).
__global__ void bpack_kernel(const float* __restrict__ W1,
                             const float* __restrict__ W2) {
    for (int i = blockIdx.x * blockDim.x + threadIdx.x; i < 2 * DD * DD;
         i += gridDim.x * blockDim.x) {
        int which = i >> 14;
        int j = i & 16383;
        float w = (which ? W2 : W1)[j];
        __nv_bfloat16 hi = __float2bfloat16(w);
        __nv_bfloat16 lo = __float2bfloat16(w - __bfloat162float(hi));
        g_Whi[which][j] = hi;
        g_Wlo[which][j] = lo;
    }
}

// ---------------- CSR aggregation: fp32 gather-sum -> bf16 hi/lo split -----
// Warp per node, lane owns one float4 of the 128-wide row. 8 accumulators
// -> 8 outstanding gathers (MLP=8). Epilogue splits the fp32 sum to bf16
// hi/lo and stores both (free: kernel is memory-bound). No smem -> high occ.
__global__ void csr_agg_kernel(const float* __restrict__ X, int N) {
    int node = (int)((blockIdx.x * blockDim.x + threadIdx.x) >> 5);
    int lane = threadIdx.x & 31;
    if (node >= N) return;
    int j   = __ldg(&g_rowptr[node]);
    int end = __ldg(&g_rowptr[node + 1]);
    float4 a0 = make_float4(0.f, 0.f, 0.f, 0.f);
    float4 a1 = a0, a2 = a0, a3 = a0, a4 = a0, a5 = a0, a6 = a0, a7 = a0;
    for (; j + 7 < end; j += 8) {
        int s0 = g_esrc[j],     s1 = g_esrc[j + 1];
        int s2 = g_esrc[j + 2], s3 = g_esrc[j + 3];
        int s4 = g_esrc[j + 4], s5 = g_esrc[j + 5];
        int s6 = g_esrc[j + 6], s7 = g_esrc[j + 7];
        float4 v0 = *(const float4*)(X + (size_t)s0 * DD + lane * 4);
        float4 v1 = *(const float4*)(X + (size_t)s1 * DD + lane * 4);
        float4 v2 = *(const float4*)(X + (size_t)s2 * DD + lane * 4);
        float4 v3 = *(const float4*)(X + (size_t)s3 * DD + lane * 4);
        float4 v4 = *(const float4*)(X + (size_t)s4 * DD + lane * 4);
        float4 v5 = *(const float4*)(X + (size_t)s5 * DD + lane * 4);
        float4 v6 = *(const float4*)(X + (size_t)s6 * DD + lane * 4);
        float4 v7 = *(const float4*)(X + (size_t)s7 * DD + lane * 4);
        a0.x += v0.x; a0.y += v0.y; a0.z += v0.z; a0.w += v0.w;
        a1.x += v1.x; a1.y += v1.y; a1.z += v1.z; a1.w += v1.w;
        a2.x += v2.x; a2.y += v2.y; a2.z += v2.z; a2.w += v2.w;
        a3.x += v3.x; a3.y += v3.y; a3.z += v3.z; a3.w += v3.w;
        a4.x += v4.x; a4.y += v4.y; a4.z += v4.z; a4.w += v4.w;
        a5.x += v5.x; a5.y += v5.y; a5.z += v5.z; a5.w += v5.w;
        a6.x += v6.x; a6.y += v6.y; a6.z += v6.z; a6.w += v6.w;
        a7.x += v7.x; a7.y += v7.y; a7.z += v7.z; a7.w += v7.w;
    }
    for (; j < end; j++) {
        int s = g_esrc[j];
        float4 v = *(const float4*)(X + (size_t)s * DD + lane * 4);
        a0.x += v.x; a0.y += v.y; a0.z += v.z; a0.w += v.w;
    }
    a0.x += a1.x + a2.x + a3.x + a4.x + a5.x + a6.x + a7.x;
    a0.y += a1.y + a2.y + a3.y + a4.y + a5.y + a6.y + a7.y;
    a0.z += a1.z + a2.z + a3.z + a4.z + a5.z + a6.z + a7.z;
    a0.w += a1.w + a2.w + a3.w + a4.w + a5.w + a6.w + a7.w;

    // split fp32 -> bf16 hi/lo; lane writes 8B to each array (coalesced)
    __nv_bfloat16 hx = __float2bfloat16(a0.x), hy = __float2bfloat16(a0.y);
    __nv_bfloat16 hz = __float2bfloat16(a0.z), hw = __float2bfloat16(a0.w);
    __nv_bfloat16 lx = __float2bfloat16(a0.x - __bfloat162float(hx));
    __nv_bfloat16 ly = __float2bfloat16(a0.y - __bfloat162float(hy));
    __nv_bfloat16 lz = __float2bfloat16(a0.z - __bfloat162float(hz));
    __nv_bfloat16 lw = __float2bfloat16(a0.w - __bfloat162float(hw));
    ushort4 hv = make_ushort4(__bfloat16_as_ushort(hx), __bfloat16_as_ushort(hy),
                              __bfloat16_as_ushort(hz), __bfloat16_as_ushort(hw));
    ushort4 lv = make_ushort4(__bfloat16_as_ushort(lx), __bfloat16_as_ushort(ly),
                              __bfloat16_as_ushort(lz), __bfloat16_as_ushort(lw));
    size_t off = (size_t)node * DD + lane * 4;
    *(ushort4*)(g_aggh + off)  = hv;
    *(ushort4*)(g_agglo + off) = lv;
}

// ---------------- tensor-core GEMM + bias + ReLU (mma.sync bf16) -----------
// CTA: 64x128 tile, 256 threads = 8 warps (2m x 4n blocks, warp tile 32x32).
// A arrives pre-split as bf16 hi/lo -> stage is a straight 16B copy.
// acc += Ahi*Whi + Alo*Whi + Ahi*Wlo (fp32 accumulate; lo*lo dropped ~2^-18)
#define PITCH 136
#define TILE_M 64
#define SM_AHI 0
#define SM_ALO (TILE_M * PITCH)
#define SM_WHI (2 * TILE_M * PITCH)
#define SM_WLO (2 * TILE_M * PITCH + 128 * PITCH)
#define GSM_TOTAL ((2 * TILE_M + 2 * 128) * PITCH * (int)sizeof(__nv_bfloat16))

__global__ __launch_bounds__(256, 2)
void mma_gemm(const __nv_bfloat16* __restrict__ Ahi,
              const __nv_bfloat16* __restrict__ Alo,
              const __nv_bfloat16* __restrict__ Whi,
              const __nv_bfloat16* __restrict__ Wlo,
              const float* __restrict__ bias, float* __restrict__ out, int N) {
    extern __shared__ __nv_bfloat16 smem[];
    const uint32_t sb = smem_u32(smem);
    const int tid = threadIdx.x;
    const int lane = tid & 31;
    const int wid = tid >> 5;
    const int row0 = blockIdx.x * TILE_M;

    // A tiles: straight 16B copies of pre-split bf16 (guard OOB rows -> 0)
    const uint4 zero4 = make_uint4(0u, 0u, 0u, 0u);
    for (int i = tid; i < TILE_M * 16; i += 256) {
        int r = i >> 4;
        int q = (i & 15) * 8;
        int gr = row0 + r;
        uint4 vh = zero4, vl = zero4;
        if (gr < N) {
            vh = *(const uint4*)(Ahi + (size_t)gr * DD + q);
            vl = *(const uint4*)(Alo + (size_t)gr * DD + q);
        }
        *(uint4*)(smem + SM_AHI + r * PITCH + q) = vh;
        *(uint4*)(smem + SM_ALO + r * PITCH + q) = vl;
    }
    // W tiles (full 128x128): straight copy, 16B chunks
    for (int i = tid; i < 128 * 16; i += 256) {
        int r = i >> 4;
        int q = (i & 15) * 8;
        *(uint4*)(smem + SM_WHI + r * PITCH + q) = *(const uint4*)(Whi + r * DD + q);
        *(uint4*)(smem + SM_WLO + r * PITCH + q) = *(const uint4*)(Wlo + r * DD + q);
    }
    __syncthreads();

    const int wm0 = (wid & 1) * 32;
    const int wc0 = (wid >> 1) * 32;

    float acc[2][4][4];
#pragma unroll
    for (int m = 0; m < 2; m++)
#pragma unroll
        for (int n = 0; n < 4; n++)
#pragma unroll
            for (int q = 0; q < 4; q++) acc[m][n][q] = 0.f;

    const int lrow = lane & 15;
    const int lkof = (lane >> 4) * 8;

#pragma unroll
    for (int kk = 0; kk < 8; kk++) {
        const int k0 = kk * 16 + lkof;
        uint32_t ah[2][4], al[2][4], bh[2][4], bl[2][4];
#pragma unroll
        for (int mt = 0; mt < 2; mt++) {
            uint32_t ra = sb + (uint32_t)(((wm0 + mt * 16 + lrow) * PITCH + k0) * 2);
            ldm_x4(ah[mt][0], ah[mt][1], ah[mt][2], ah[mt][3], ra + SM_AHI * 2);
            ldm_x4(al[mt][0], al[mt][1], al[mt][2], al[mt][3], ra + SM_ALO * 2);
        }
#pragma unroll
        for (int np = 0; np < 2; np++) {
            uint32_t rb = sb + (uint32_t)(((wc0 + np * 16 + lrow) * PITCH + k0) * 2);
            ldm_x4(bh[np][0], bh[np][1], bh[np][2], bh[np][3], rb + SM_WHI * 2);
            ldm_x4(bl[np][0], bl[np][1], bl[np][2], bl[np][3], rb + SM_WLO * 2);
        }
#pragma unroll
        for (int mt = 0; mt < 2; mt++)
#pragma unroll
            for (int np = 0; np < 2; np++) {
                mma_bf16(acc[mt][2 * np],     ah[mt], bh[np][0], bh[np][2]);
                mma_bf16(acc[mt][2 * np + 1], ah[mt], bh[np][1], bh[np][3]);
                mma_bf16(acc[mt][2 * np],     al[mt], bh[np][0], bh[np][2]);
                mma_bf16(acc[mt][2 * np + 1], al[mt], bh[np][1], bh[np][3]);
                mma_bf16(acc[mt][2 * np],     ah[mt], bl[np][0], bl[np][2]);
                mma_bf16(acc[mt][2 * np + 1], ah[mt], bl[np][1], bl[np][3]);
            }
    }

    // Epilogue: bias + ReLU
    const int erow = lane >> 2;
    const int ecol = (lane & 3) * 2;
    float bb[4][2];
#pragma unroll
    for (int nt = 0; nt < 4; nt++) {
        bb[nt][0] = bias[wc0 + nt * 8 + ecol];
        bb[nt][1] = bias[wc0 + nt * 8 + ecol + 1];
    }
#pragma unroll
    for (int mt = 0; mt < 2; mt++) {
#pragma unroll
        for (int half = 0; half < 2; half++) {
            int gr = row0 + wm0 + mt * 16 + erow + half * 8;
            if (gr < N) {
                float* op = out + (size_t)gr * DD + wc0;
#pragma unroll
                for (int nt = 0; nt < 4; nt++) {
                    float2 o;
                    o.x = fmaxf(acc[mt][nt][2 * half]     + bb[nt][0], 0.f);
                    o.y = fmaxf(acc[mt][nt][2 * half + 1] + bb[nt][1], 0.f);
                    *(float2*)(op + nt * 8 + ecol) = o;
                }
            }
        }
    }
}

// ---------------------------------------------------------------------------
extern "C" void kernel_launch(void* const* d_in, const int* in_sizes, int n_in,
                              void* d_out, int out_size) {
    const float* x  = (const float*)d_in[0];
    const void*  ei = d_in[1];
    const float* W1 = (const float*)d_in[2];
    const float* b1 = (const float*)d_in[3];
    const float* W2 = (const float*)d_in[4];
    const float* b2 = (const float*)d_in[5];
    float* out      = (float*)d_out;

    int N = in_sizes[0] / DD;
    int E = in_sizes[1] / 2;

    float* h;
    __nv_bfloat16 *aggh, *agglo, *wh1, *wl1, *wh2, *wl2;
    cudaGetSymbolAddress((void**)&h, g_h);
    cudaGetSymbolAddress((void**)&aggh, g_aggh);
    cudaGetSymbolAddress((void**)&agglo, g_agglo);
    cudaGetSymbolAddress((void**)&wh1, g_Whi);
    cudaGetSymbolAddress((void**)&wl1, g_Wlo);
    wh2 = wh1 + DD * DD;
    wl2 = wl1 + DD * DD;

    cudaFuncSetAttribute(mma_gemm, cudaFuncAttributeMaxDynamicSharedMemorySize,
                         GSM_TOTAL);

    int n       = N + 1;
    int nb      = (n + SCAN_CHUNK - 1) / SCAN_CHUNK;
    int cgrid   = (E + 255) / 256;
    int agrid   = (N * 32 + 255) / 256;   // warp per node
    int ggrid   = (N + TILE_M - 1) / TILE_M;
    int n_check = E < 8 ? E : 8;

    // Build CSR + packed weights (once; reused by both layers)
    detect_kernel<<<1, 1>>>(ei, n_check, N);
    zero_cnt_kernel<<<(n + 255) / 256, 256>>>(n);
    convert_hist_kernel<<<cgrid, 256>>>(ei, E, N);
    scan1_kernel<<<nb, SCAN_CHUNK>>>(n);
    scan2_kernel<<<1, 32>>>(nb);
    scan3_kernel<<<(n + 255) / 256, 256>>>(n, N);
    place_kernel<<<cgrid, 256>>>(E);
    bpack_kernel<<<64, 256>>>(W1, W2);

    // Layer 1: aggregate(x) -> bf16 hi/lo, then tensor GEMM
    csr_agg_kernel<<<agrid, 256>>>(x, N);
    mma_gemm<<<ggrid, 256, GSM_TOTAL>>>(aggh, agglo, wh1, wl1, b1, h, N);

    // Layer 2: aggregate(h) -> bf16 hi/lo, then tensor GEMM
    csr_agg_kernel<<<agrid, 256>>>(h, N);
    mma_gemm<<<ggrid, 256, GSM_TOTAL>>>(aggh, agglo, wh2, wl2, b2, out, N);
}